// round 7
// baseline (speedup 1.0000x reference)
#include <cuda_runtime.h>
#include <cstdint>

#define T_STEPS 512
#define BATCH   2048
#define IN_DIM  12
#define E_DIM   15
#define H_DIM   20
#define ROWS_PB 7
#define NTHREADS (ROWS_PB * H_DIM)                  // 140
#define NGRID   ((BATCH + ROWS_PB - 1) / ROWS_PB)   // 293 -> 2 blocks/SM
#define CHUNK   8                                   // X prefetch chunk (steps)
#define XPT     (ROWS_PB * IN_DIM)                  // 84 x-elements per step

// ---- packed f32x2 helpers (Blackwell sm_103a) ----
__device__ __forceinline__ unsigned long long pack2(float x, float y) {
    unsigned long long u;
    asm("mov.b64 %0, {%1, %2};" : "=l"(u) : "f"(x), "f"(y));
    return u;
}
__device__ __forceinline__ void fma2(unsigned long long& d,
                                     unsigned long long a,
                                     unsigned long long b) {
    asm("fma.rn.f32x2 %0, %1, %2, %0;" : "+l"(d) : "l"(a), "l"(b));
}
__device__ __forceinline__ float hsum2(unsigned long long u) {
    float x, y;
    asm("mov.b64 {%0, %1}, %2;" : "=f"(x), "=f"(y) : "l"(u));
    return x + y;
}
__device__ __forceinline__ float tanh_a(float x) {
    float y;
    asm("tanh.approx.f32 %0, %1;" : "=f"(y) : "f"(x));
    return y;
}
__device__ __forceinline__ float sig_a(float x) {        // sigmoid, 1 MUFU
    return fmaf(0.5f, tanh_a(0.5f * x), 0.5f);
}
// 16B shared load (4 floats) into two aligned u64 pairs (feeds fma.rn.f32x2)
__device__ __forceinline__ void lds2(unsigned long long& a, unsigned long long& b,
                                     const float* p) {
    uint32_t addr = (uint32_t)__cvta_generic_to_shared(p);
    asm volatile("ld.shared.v2.b64 {%0, %1}, [%2];" : "=l"(a), "=l"(b) : "r"(addr));
}

__global__ void __launch_bounds__(NTHREADS, 2)
lstm_tracker_kernel(const float* __restrict__ X,
                    const float* __restrict__ Wemb, const float* __restrict__ bemb,
                    const float* __restrict__ Wih,  const float* __restrict__ bih,
                    const float* __restrict__ Whh,  const float* __restrict__ bhh,
                    const float* __restrict__ Wout, const float* __restrict__ bout,
                    float* __restrict__ out)
{
    __shared__ __align__(16) float s_wemb[E_DIM * IN_DIM];
    __shared__ __align__(16) float s_wih[4 * H_DIM * E_DIM];
    __shared__ float s_bemb[E_DIM];
    __shared__ __align__(16) float x_s[2][CHUNK][XPT];       // chunked double buffer
    __shared__ __align__(16) float h_s[2][ROWS_PB][H_DIM];   // ping-pong h

    const int tid  = threadIdx.x;
    const int row  = tid / H_DIM;        // local batch row 0..6
    const int k    = tid % H_DIM;        // hidden unit owned by this thread
    const int grow = blockIdx.x * ROWS_PB + row;
    const bool valid = grow < BATCH;

    // ---- cooperative weight staging ----
    for (int i = tid; i < E_DIM * IN_DIM; i += NTHREADS)     s_wemb[i] = Wemb[i];
    for (int i = tid; i < 4 * H_DIM * E_DIM; i += NTHREADS)  s_wih[i]  = Wih[i];
    if (tid < E_DIM) s_bemb[tid] = bemb[tid];
    h_s[0][row][k] = 0.0f;
    h_s[1][row][k] = 0.0f;
    __syncthreads();

    // ---- per-thread register weights (invariant over t) ----
    // Fused: Wc[r][j] = sum_e Wih[r][e]*Wemb[e][j],  r = g*H + k
    //        bc[g]    = bih[r] + bhh[r] + sum_e Wih[r][e]*bemb[e]
    float bc[4];
    unsigned long long wc[4][IN_DIM / 2];   // 24 u64
    unsigned long long wh[4][H_DIM / 2];    // 40 u64
#pragma unroll
    for (int g = 0; g < 4; ++g) {
        const int r = g * H_DIM + k;
        float b = bih[r] + bhh[r];
#pragma unroll
        for (int e = 0; e < E_DIM; ++e) b += s_wih[r * E_DIM + e] * s_bemb[e];
        bc[g] = b;
#pragma unroll
        for (int jj = 0; jj < IN_DIM / 2; ++jj) {
            float c0 = 0.0f, c1 = 0.0f;
#pragma unroll
            for (int e = 0; e < E_DIM; ++e) {
                const float wie = s_wih[r * E_DIM + e];
                c0 += wie * s_wemb[e * IN_DIM + 2 * jj];
                c1 += wie * s_wemb[e * IN_DIM + 2 * jj + 1];
            }
            wc[g][jj] = pack2(c0, c1);
        }
#pragma unroll
        for (int jj = 0; jj < H_DIM / 2; ++jj)
            wh[g][jj] = pack2(Whh[r * H_DIM + 2 * jj], Whh[r * H_DIM + 2 * jj + 1]);
    }

    // hoisted out-projection weights (only meaningful for k<3 threads)
    const bool doOut = (k < 3) && valid;
    float bo = 0.0f;
    unsigned long long wo[H_DIM / 2];
    if (k < 3) {
        bo = bout[k];
#pragma unroll
        for (int jj = 0; jj < H_DIM / 2; ++jj)
            wo[jj] = pack2(Wout[k * H_DIM + 2 * jj], Wout[k * H_DIM + 2 * jj + 1]);
    } else {
#pragma unroll
        for (int jj = 0; jj < H_DIM / 2; ++jj) wo[jj] = 0ull;
    }

    // ---- X prefetch prologue ----
    const int  xbase = blockIdx.x * XPT;
    const bool isPre = (tid < XPT) && (xbase + tid < BATCH * IN_DIM);
    const long long xstride = (long long)BATCH * IN_DIM;
    float xr[CHUNK];
    if (isPre) {
#pragma unroll
        for (int s = 0; s < CHUNK; ++s)
            x_s[0][s][tid] = X[(long long)s * xstride + xbase + tid];
#pragma unroll
        for (int s = 0; s < CHUNK; ++s)
            xr[s] = X[(long long)(CHUNK + s) * xstride + xbase + tid];
    }
    float c = 0.0f;
    __syncthreads();

    int buf = 0;

    for (int t = 0; t < T_STEPS; ++t) {
        // chunk boundary: stage chunk (t/8 + 1) from regs, LDG chunk (t/8 + 2)
        if ((t & (CHUNK - 1)) == 0 && (t + CHUNK) < T_STEPS && isPre) {
            const int nb = ((t >> 3) + 1) & 1;
#pragma unroll
            for (int s = 0; s < CHUNK; ++s) x_s[nb][s][tid] = xr[s];
            const int bt = t + 2 * CHUNK;
#pragma unroll
            for (int s = 0; s < CHUNK; ++s)
                xr[s] = (bt + s < T_STEPS)
                      ? X[(long long)(bt + s) * xstride + xbase + tid] : 0.0f;
        }

        // ---- 4 gate dot-products, operands pre-packed via LDS.128 ----
        unsigned long long a0 = pack2(bc[0], 0.0f);
        unsigned long long a1 = pack2(bc[1], 0.0f);
        unsigned long long a2 = pack2(bc[2], 0.0f);
        unsigned long long a3 = pack2(bc[3], 0.0f);

        const float* xp = &x_s[(t >> 3) & 1][t & (CHUNK - 1)][row * IN_DIM];
        unsigned long long q0, q1, q2, q3, q4, q5;
        lds2(q0, q1, xp);        // x[0..3]
        lds2(q2, q3, xp + 4);    // x[4..7]
        lds2(q4, q5, xp + 8);    // x[8..11]
        fma2(a0, wc[0][0], q0); fma2(a1, wc[1][0], q0); fma2(a2, wc[2][0], q0); fma2(a3, wc[3][0], q0);
        fma2(a0, wc[0][1], q1); fma2(a1, wc[1][1], q1); fma2(a2, wc[2][1], q1); fma2(a3, wc[3][1], q1);
        fma2(a0, wc[0][2], q2); fma2(a1, wc[1][2], q2); fma2(a2, wc[2][2], q2); fma2(a3, wc[3][2], q2);
        fma2(a0, wc[0][3], q3); fma2(a1, wc[1][3], q3); fma2(a2, wc[2][3], q3); fma2(a3, wc[3][3], q3);
        fma2(a0, wc[0][4], q4); fma2(a1, wc[1][4], q4); fma2(a2, wc[2][4], q4); fma2(a3, wc[3][4], q4);
        fma2(a0, wc[0][5], q5); fma2(a1, wc[1][5], q5); fma2(a2, wc[2][5], q5); fma2(a3, wc[3][5], q5);

        unsigned long long hq[10];
        const float* hp = h_s[buf][row];
        lds2(hq[0], hq[1], hp);
        lds2(hq[2], hq[3], hp + 4);
        lds2(hq[4], hq[5], hp + 8);
        lds2(hq[6], hq[7], hp + 12);
        lds2(hq[8], hq[9], hp + 16);
#pragma unroll
        for (int jj = 0; jj < H_DIM / 2; ++jj) {
            fma2(a0, wh[0][jj], hq[jj]);
            fma2(a1, wh[1][jj], hq[jj]);
            fma2(a2, wh[2][jj], hq[jj]);
            fma2(a3, wh[3][jj], hq[jj]);
        }

        const float iv = sig_a(hsum2(a0));
        const float fv = sig_a(hsum2(a1));
        const float gv = tanh_a(hsum2(a2));
        const float ov = sig_a(hsum2(a3));
        c = fmaf(fv, c, iv * gv);
        h_s[buf ^ 1][row][k] = ov * tanh_a(c);

        // out-projection for step t-1 (hq = h_{t-1}; weights in registers)
        if (doOut && t > 0) {
            unsigned long long oa = pack2(bo, 0.0f);
#pragma unroll
            for (int jj = 0; jj < H_DIM / 2; ++jj) fma2(oa, wo[jj], hq[jj]);
            out[(long long)(t - 1) * (BATCH * 3) + grow * 3 + k] = hsum2(oa);
        }

        __syncthreads();
        buf ^= 1;
    }

    // final output for t = T-1 (h_{T-1} lives in h_s[buf])
    if (doOut) {
        unsigned long long hq2[10];
        const float* hp = h_s[buf][row];
        lds2(hq2[0], hq2[1], hp);
        lds2(hq2[2], hq2[3], hp + 4);
        lds2(hq2[4], hq2[5], hp + 8);
        lds2(hq2[6], hq2[7], hp + 12);
        lds2(hq2[8], hq2[9], hp + 16);
        unsigned long long oa = pack2(bo, 0.0f);
#pragma unroll
        for (int jj = 0; jj < H_DIM / 2; ++jj) fma2(oa, wo[jj], hq2[jj]);
        out[(long long)(T_STEPS - 1) * (BATCH * 3) + grow * 3 + k] = hsum2(oa);
    }
}

extern "C" void kernel_launch(void* const* d_in, const int* in_sizes, int n_in,
                              void* d_out, int out_size) {
    const float* X    = (const float*)d_in[0];
    const float* Wemb = (const float*)d_in[1];
    const float* bemb = (const float*)d_in[2];
    const float* Wih  = (const float*)d_in[3];
    const float* bih  = (const float*)d_in[4];
    const float* Whh  = (const float*)d_in[5];
    const float* bhh  = (const float*)d_in[6];
    const float* Wout = (const float*)d_in[7];
    const float* bout = (const float*)d_in[8];
    float* out = (float*)d_out;

    lstm_tracker_kernel<<<NGRID, NTHREADS>>>(X, Wemb, bemb, Wih, bih,
                                             Whh, bhh, Wout, bout, out);
}

// round 8
// speedup vs baseline: 1.2179x; 1.2179x over previous
#include <cuda_runtime.h>
#include <cstdint>

#define T_STEPS 512
#define BATCH   2048
#define IN_DIM  12
#define E_DIM   15
#define H_DIM   20
#define CHUNK   8
#define XS      (BATCH * IN_DIM)      // x stride per timestep
#define OS      (BATCH * 3)           // out stride per timestep

typedef unsigned long long u64;

// ---- packed f32x2 helpers (Blackwell sm_103a) ----
__device__ __forceinline__ u64 pack2(float x, float y) {
    u64 u; asm("mov.b64 %0, {%1, %2};" : "=l"(u) : "f"(x), "f"(y)); return u;
}
__device__ __forceinline__ void unpack2(float& x, float& y, u64 u) {
    asm("mov.b64 {%0, %1}, %2;" : "=f"(x), "=f"(y) : "l"(u));
}
__device__ __forceinline__ void fma2(u64& d, u64 a, u64 b) {
    asm("fma.rn.f32x2 %0, %1, %2, %0;" : "+l"(d) : "l"(a), "l"(b));
}
__device__ __forceinline__ float hsum2(u64 u) {
    float x, y; unpack2(x, y, u); return x + y;
}
__device__ __forceinline__ float tanh_a(float x) {
    float y; asm("tanh.approx.f32 %0, %1;" : "=f"(y) : "f"(x)); return y;
}
__device__ __forceinline__ float sig_a(float x) {
    return fmaf(0.5f, tanh_a(0.5f * x), 0.5f);
}
// 16B shared load into two u64 (generic pointer must be 16B aligned smem)
__device__ __forceinline__ void lds2(u64& a, u64& b, const void* p) {
    uint32_t addr = (uint32_t)__cvta_generic_to_shared(p);
    asm volatile("ld.shared.v2.b64 {%0, %1}, [%2];" : "=l"(a), "=l"(b) : "r"(addr));
}

__global__ void __launch_bounds__(32, 14)
lstm_tracker_kernel(const float* __restrict__ X,
                    const float* __restrict__ Wemb, const float* __restrict__ bemb,
                    const float* __restrict__ Wih,  const float* __restrict__ bih,
                    const float* __restrict__ Whh,  const float* __restrict__ bhh,
                    const float* __restrict__ Wout, const float* __restrict__ bout,
                    float* __restrict__ out)
{
    // one warp == one batch row; all smem is warp-private
    __shared__ __align__(16) u64   wc_s[80 * 6];              // fused x-gate weights, packed pairs
    __shared__ float               bc_s[80];                  // fused bias
    __shared__ __align__(16) float xg_s[2][CHUNK][H_DIM][4];  // precomputed x-gates (i,f,g,o per cell)
    __shared__ __align__(16) float x_s[2][CHUNK][IN_DIM];     // staged raw x
    __shared__ __align__(16) u64   hdup[2][H_DIM];            // h duplicated: (h_j, h_j)
    __shared__ __align__(16) float hlin[2][H_DIM];            // h linear (for out-proj)

    const int lane = threadIdx.x;
    const int grow = blockIdx.x;          // batch row

    // ---- init: fused x-gate weights Wc = Wih @ Wemb, bias bc ----
    for (int i = lane; i < 480; i += 32) {              // 80 gates x 6 pair-cols
        const int r = i / 6, jj = i - r * 6;
        float c0 = 0.f, c1 = 0.f;
#pragma unroll
        for (int e = 0; e < E_DIM; ++e) {
            const float wie = Wih[r * E_DIM + e];
            c0 += wie * Wemb[e * IN_DIM + 2 * jj];
            c1 += wie * Wemb[e * IN_DIM + 2 * jj + 1];
        }
        wc_s[r * 6 + jj] = pack2(c0, c1);
    }
    for (int r = lane; r < 80; r += 32) {
        float b = bih[r] + bhh[r];
#pragma unroll
        for (int e = 0; e < E_DIM; ++e) b += Wih[r * E_DIM + e] * bemb[e];
        bc_s[r] = b;
    }

    // ---- per-lane recurrent weights (gate pairs packed) / out-proj overlay ----
    u64 wh01[H_DIM], wh23[H_DIM];   // lanes <20: ((Wi,Wf)[j]), ((Wg,Wo)[j])
    float bo = 0.f;
    if (lane < H_DIM) {
#pragma unroll
        for (int j = 0; j < H_DIM; ++j) {
            wh01[j] = pack2(Whh[(0 * H_DIM + lane) * H_DIM + j],
                            Whh[(1 * H_DIM + lane) * H_DIM + j]);
            wh23[j] = pack2(Whh[(2 * H_DIM + lane) * H_DIM + j],
                            Whh[(3 * H_DIM + lane) * H_DIM + j]);
        }
    } else {
#pragma unroll
        for (int j = 0; j < H_DIM; ++j) { wh01[j] = 0ull; wh23[j] = 0ull; }
        if (lane < 23) {                 // lanes 20..22 own out rows 0..2
            const int m = lane - 20;
            bo = bout[m];
#pragma unroll
            for (int jj = 0; jj < H_DIM / 2; ++jj)
                wh01[jj] = pack2(Wout[m * H_DIM + 2 * jj], Wout[m * H_DIM + 2 * jj + 1]);
        }
    }

    // h = 0
    if (lane < H_DIM) {
        hdup[0][lane] = 0ull; hdup[1][lane] = 0ull;
        hlin[0][lane] = 0.f;  hlin[1][lane] = 0.f;
    }

    // ---- stage x chunk 0 directly; hold chunk 1 in regs ----
    for (int i = lane; i < CHUNK * IN_DIM; i += 32) {
        const int s = i / IN_DIM, j = i - s * IN_DIM;
        x_s[0][s][j] = X[(long long)s * XS + grow * IN_DIM + j];
    }
    float xr[3];
#pragma unroll
    for (int m = 0; m < 3; ++m) {
        const int i = lane + 32 * m;
        const int s = i / IN_DIM, j = i - s * IN_DIM;
        xr[m] = X[(long long)(CHUNK + s) * XS + grow * IN_DIM + j];
    }
    __syncwarp();

    // ---- precompute x-gates for chunk 0 ----
    for (int i = lane; i < CHUNK * 80; i += 32) {
        const int s = i / 80, r = i - s * 80;
        u64 acc = pack2(bc_s[r], 0.f);
        u64 x0, x1, x2, x3, x4, x5, w0, w1, w2, w3, w4, w5;
        const float* xp = x_s[0][s];
        lds2(x0, x1, xp); lds2(x2, x3, xp + 4); lds2(x4, x5, xp + 8);
        const u64* wp = &wc_s[r * 6];
        lds2(w0, w1, wp); lds2(w2, w3, wp + 2); lds2(w4, w5, wp + 4);
        fma2(acc, w0, x0); fma2(acc, w1, x1); fma2(acc, w2, x2);
        fma2(acc, w3, x3); fma2(acc, w4, x4); fma2(acc, w5, x5);
        xg_s[0][s][r % H_DIM][r / H_DIM] = hsum2(acc);
    }
    __syncwarp();

    float c = 0.f;
    int buf = 0;

    for (int t = 0; t < T_STEPS; ++t) {
        const int cb = (t >> 3) & 1;
        const int s  = t & (CHUNK - 1);

        // ---- chunk boundary: stage x from regs, prefetch next, precompute xg ----
        if (s == 0 && t > 0) {
#pragma unroll
            for (int m = 0; m < 3; ++m) {
                const int i = lane + 32 * m;
                x_s[cb][i / IN_DIM][i % IN_DIM] = xr[m];
            }
            if (t + 2 * CHUNK <= T_STEPS) {
#pragma unroll
                for (int m = 0; m < 3; ++m) {
                    const int i = lane + 32 * m;
                    const int ss = i / IN_DIM, j = i - ss * IN_DIM;
                    xr[m] = X[(long long)(t + CHUNK + ss) * XS + grow * IN_DIM + j];
                }
            }
            __syncwarp();
            for (int i = lane; i < CHUNK * 80; i += 32) {
                const int ps = i / 80, r = i - ps * 80;
                u64 acc = pack2(bc_s[r], 0.f);
                u64 x0, x1, x2, x3, x4, x5, w0, w1, w2, w3, w4, w5;
                const float* xp = x_s[cb][ps];
                lds2(x0, x1, xp); lds2(x2, x3, xp + 4); lds2(x4, x5, xp + 8);
                const u64* wp = &wc_s[r * 6];
                lds2(w0, w1, wp); lds2(w2, w3, wp + 2); lds2(w4, w5, wp + 4);
                fma2(acc, w0, x0); fma2(acc, w1, x1); fma2(acc, w2, x2);
                fma2(acc, w3, x3); fma2(acc, w4, x4); fma2(acc, w5, x5);
                xg_s[cb][ps][r % H_DIM][r / H_DIM] = hsum2(acc);
            }
            __syncwarp();
        }

        // ---- recurrent step ----
        if (lane < H_DIM) {
            u64 a01, a23;
            lds2(a01, a23, &xg_s[cb][s][lane][0]);   // (i,f) and (g,o) x-gate init

            const u64* hp = hdup[buf];
#pragma unroll
            for (int q = 0; q < 5; ++q) {             // 20 dup-h values, 4 per group
                u64 e0, e1, e2, e3;
                lds2(e0, e1, hp + 4 * q);
                lds2(e2, e3, hp + 4 * q + 2);
                fma2(a01, wh01[4 * q],     e0); fma2(a23, wh23[4 * q],     e0);
                fma2(a01, wh01[4 * q + 1], e1); fma2(a23, wh23[4 * q + 1], e1);
                fma2(a01, wh01[4 * q + 2], e2); fma2(a23, wh23[4 * q + 2], e2);
                fma2(a01, wh01[4 * q + 3], e3); fma2(a23, wh23[4 * q + 3], e3);
            }
            float pi, pf, pg, po;
            unpack2(pi, pf, a01);
            unpack2(pg, po, a23);
            pi = sig_a(pi); pf = sig_a(pf); pg = tanh_a(pg); po = sig_a(po);
            c = fmaf(pf, c, pi * pg);
            const float h = po * tanh_a(c);
            hdup[buf ^ 1][lane] = pack2(h, h);
            hlin[buf ^ 1][lane] = h;
        } else if (lane < 23 && t > 0) {
            // out[t-1] from h_{t-1} (= hlin[buf], stable this step)
            u64 acc = pack2(bo, 0.f);
            const float* hp = hlin[buf];
            u64 g0, g1, g2, g3;
            lds2(g0, g1, hp);      fma2(acc, wh01[0], g0); fma2(acc, wh01[1], g1);
            lds2(g2, g3, hp + 4);  fma2(acc, wh01[2], g2); fma2(acc, wh01[3], g3);
            lds2(g0, g1, hp + 8);  fma2(acc, wh01[4], g0); fma2(acc, wh01[5], g1);
            lds2(g2, g3, hp + 12); fma2(acc, wh01[6], g2); fma2(acc, wh01[7], g3);
            lds2(g0, g1, hp + 16); fma2(acc, wh01[8], g0); fma2(acc, wh01[9], g1);
            out[(long long)(t - 1) * OS + grow * 3 + (lane - 20)] = hsum2(acc);
        }
        __syncwarp();
        buf ^= 1;
    }

    // final out[T-1] from hlin[buf]
    if (lane >= H_DIM && lane < 23) {
        u64 acc = pack2(bo, 0.f);
        const float* hp = hlin[buf];
        u64 g0, g1, g2, g3;
        lds2(g0, g1, hp);      fma2(acc, wh01[0], g0); fma2(acc, wh01[1], g1);
        lds2(g2, g3, hp + 4);  fma2(acc, wh01[2], g2); fma2(acc, wh01[3], g3);
        lds2(g0, g1, hp + 8);  fma2(acc, wh01[4], g0); fma2(acc, wh01[5], g1);
        lds2(g2, g3, hp + 12); fma2(acc, wh01[6], g2); fma2(acc, wh01[7], g3);
        lds2(g0, g1, hp + 16); fma2(acc, wh01[8], g0); fma2(acc, wh01[9], g1);
        out[(long long)(T_STEPS - 1) * OS + grow * 3 + (lane - 20)] = hsum2(acc);
    }
}

extern "C" void kernel_launch(void* const* d_in, const int* in_sizes, int n_in,
                              void* d_out, int out_size) {
    const float* X    = (const float*)d_in[0];
    const float* Wemb = (const float*)d_in[1];
    const float* bemb = (const float*)d_in[2];
    const float* Wih  = (const float*)d_in[3];
    const float* bih  = (const float*)d_in[4];
    const float* Whh  = (const float*)d_in[5];
    const float* bhh  = (const float*)d_in[6];
    const float* Wout = (const float*)d_in[7];
    const float* bout = (const float*)d_in[8];
    float* out = (float*)d_out;

    lstm_tracker_kernel<<<BATCH, 32>>>(X, Wemb, bemb, Wih, bih,
                                       Whh, bhh, Wout, bout, out);
}

// round 9
// speedup vs baseline: 1.3069x; 1.0731x over previous
#include <cuda_runtime.h>
#include <cstdint>

#define T_STEPS 512
#define BATCH   2048
#define IN_DIM  12
#define E_DIM   15
#define H_DIM   20
#define CHUNK   8
#define NCHUNK  (T_STEPS / CHUNK)     // 64
#define XS      (BATCH * IN_DIM)
#define OS      (BATCH * 3)

typedef unsigned long long u64;
typedef uint32_t u32;

__device__ __forceinline__ u64 pack2(float x, float y) {
    u64 u; asm("mov.b64 %0, {%1, %2};" : "=l"(u) : "f"(x), "f"(y)); return u;
}
__device__ __forceinline__ void unpack2(float& x, float& y, u64 u) {
    asm("mov.b64 {%0, %1}, %2;" : "=f"(x), "=f"(y) : "l"(u));
}
__device__ __forceinline__ void fma2(u64& d, u64 a, u64 b) {
    asm("fma.rn.f32x2 %0, %1, %2, %0;" : "+l"(d) : "l"(a), "l"(b));
}
__device__ __forceinline__ float tanh_a(float x) {
    float y; asm("tanh.approx.f32 %0, %1;" : "=f"(y) : "f"(x)); return y;
}
__device__ __forceinline__ float sig_a(float x) {
    return fmaf(0.5f, tanh_a(0.5f * x), 0.5f);
}
__device__ __forceinline__ u32 saddr(const void* p) {
    return (u32)__cvta_generic_to_shared(p);
}
__device__ __forceinline__ void lds2d(u64& a, u64& b, u32 addr) {
    asm volatile("ld.shared.v2.b64 {%0, %1}, [%2];" : "=l"(a), "=l"(b) : "r"(addr));
}
__device__ __forceinline__ void lds1d(u64& a, u32 addr) {
    asm volatile("ld.shared.b64 %0, [%1];" : "=l"(a) : "r"(addr));
}
__device__ __forceinline__ void sts64d(u32 addr, u64 v) {
    asm volatile("st.shared.b64 [%0], %1;" :: "r"(addr), "l"(v));
}

__global__ void __launch_bounds__(64, 7)
lstm_tracker_kernel(const float* __restrict__ X,
                    const float* __restrict__ Wemb, const float* __restrict__ bemb,
                    const float* __restrict__ Wih,  const float* __restrict__ bih,
                    const float* __restrict__ Whh,  const float* __restrict__ bhh,
                    const float* __restrict__ Wout, const float* __restrict__ bout,
                    float* __restrict__ out)
{
    // block = 2 independent warps (2 batch rows) sharing the fused tables
    __shared__ __align__(16) u64 wcp[40][12];          // pair-packed fused x weights
    __shared__ __align__(16) u64 bcp[40];              // pair-packed fused bias
    __shared__ __align__(16) u64 xdup[2][CHUNK][IN_DIM];   // (x,x) dups, per warp
    __shared__ __align__(16) u64 xg[2][CHUNK][24][2];  // x-gate pairs; slots 20-23: out-bias
    __shared__ __align__(16) u64 hdup[2][2][H_DIM];    // (h,h), [warp][buf][cell]

    const int tid  = threadIdx.x;
    const int w    = tid >> 5;
    const int lane = tid & 31;
    const int grow = blockIdx.x * 2 + w;
    const bool hLane = lane < H_DIM;
    const bool oLane = (lane >= 20) && (lane < 23);

    // ---- init fused pair weights Wc = Wih@Wemb (pairs (i,f) p<20, (g,o) p>=20) ----
    for (int i = tid; i < 480; i += 64) {
        const int p = i / 12, j = i - p * 12;
        const int gA = (p < 20) ? p : (p + 20);
        const int gB = gA + 20;
        float a = 0.f, b = 0.f;
#pragma unroll
        for (int e = 0; e < E_DIM; ++e) {
            const float we = Wemb[e * IN_DIM + j];
            a += Wih[gA * E_DIM + e] * we;
            b += Wih[gB * E_DIM + e] * we;
        }
        wcp[p][j] = pack2(a, b);
    }
    for (int p = tid; p < 40; p += 64) {
        const int gA = (p < 20) ? p : (p + 20);
        const int gB = gA + 20;
        float a = bih[gA] + bhh[gA], b = bih[gB] + bhh[gB];
#pragma unroll
        for (int e = 0; e < E_DIM; ++e) {
            a += Wih[gA * E_DIM + e] * bemb[e];
            b += Wih[gB * E_DIM + e] * bemb[e];
        }
        bcp[p] = pack2(a, b);
    }
    {   // out-lane xg slots: [w2][s][20+q][0] = (bout[q],0); slot 23 and [..][1] = 0
        const int w2 = tid >> 5, r = tid & 31;
        const int s = r >> 2, q = r & 3;
        xg[w2][s][20 + q][0] = (q < 3) ? pack2(bout[q], 0.f) : 0ull;
        xg[w2][s][20 + q][1] = 0ull;
    }
    if (hLane) hdup[w][0][lane] = 0ull;
    __syncthreads();

    // ---- per-lane register weights ----
    u64 wh01[H_DIM], wh23[H_DIM];
    if (hLane) {
#pragma unroll
        for (int j = 0; j < H_DIM; ++j) {
            wh01[j] = pack2(Whh[(lane) * H_DIM + j],      Whh[(20 + lane) * H_DIM + j]);
            wh23[j] = pack2(Whh[(40 + lane) * H_DIM + j], Whh[(60 + lane) * H_DIM + j]);
        }
    } else if (oLane) {
        const int m = lane - 20;
#pragma unroll
        for (int j = 0; j < H_DIM; ++j) {
            wh01[j] = pack2(Wout[m * H_DIM + j], 0.f);
            wh23[j] = 0ull;
        }
    } else {
#pragma unroll
        for (int j = 0; j < H_DIM; ++j) { wh01[j] = 0ull; wh23[j] = 0ull; }
    }

    // ---- staging lane assignments (96 = 8 steps x 12 per chunk, 3 per lane) ----
    int si[3], ji[3];
#pragma unroll
    for (int m = 0; m < 3; ++m) {
        const int i = lane + 32 * m;
        si[m] = i / 12; ji[m] = i - si[m] * 12;
    }

    const long long xro = (long long)grow * IN_DIM;
    // chunk 0 -> xdup directly; chunk 1 -> regs
#pragma unroll
    for (int m = 0; m < 3; ++m) {
        const float v = X[(long long)si[m] * XS + xro + ji[m]];
        xdup[w][si[m]][ji[m]] = pack2(v, v);
    }
    float xr[3];
#pragma unroll
    for (int m = 0; m < 3; ++m)
        xr[m] = X[(long long)(CHUNK + si[m]) * XS + xro + ji[m]];
    __syncwarp();

    // ---- precomputed shared addresses ----
    const int  kc       = (lane < 23) ? lane : 23;
    const u32  xg_base  = saddr(&xg[w][0][0][0]);
    const u32  myxg     = saddr(&xg[w][0][kc][0]);
    const u32  h_rd0    = saddr(&hdup[w][0][0]);
    const u32  h_rd1    = saddr(&hdup[w][1][0]);
    const u32  h_my0    = h_rd0 + lane * 8;
    const u32  h_my1    = h_rd1 + lane * 8;
    const u32  xd_base  = saddr(&xdup[w][0][0]);
    const u32  wcp_base = saddr(&wcp[0][0]);
    const u32  bcp_base = saddr(&bcp[0]);

    float c = 0.f;
    float* outp = out + (long long)grow * 3 + (lane - 20) - OS;  // only deref'd by oLane at t>0

    for (int ch = 0; ch < NCHUNK; ++ch) {
        // ---- chunk boundary: stage x, prefetch next, precompute x-gates ----
        if (ch > 0) {
#pragma unroll
            for (int m = 0; m < 3; ++m)
                xdup[w][si[m]][ji[m]] = pack2(xr[m], xr[m]);
            __syncwarp();
            if (ch + 1 < NCHUNK) {
                const long long tb = (long long)(ch + 1) * CHUNK;
#pragma unroll
                for (int m = 0; m < 3; ++m)
                    xr[m] = X[(tb + si[m]) * XS + xro + ji[m]];
            }
        }
#pragma unroll
        for (int it = 0; it < 10; ++it) {
            const int id = lane + 32 * it;          // 0..319
            const int s  = (id * 205) >> 13;        // id / 40
            const int p  = id - s * 40;
            u64 acc; lds1d(acc, bcp_base + p * 8);
            const u32 xa = xd_base + s * 96;
            const u32 wa = wcp_base + p * 96;
            u64 xv[12], wv[12];
            lds2d(xv[0], xv[1],  xa);      lds2d(xv[2], xv[3],  xa + 16);
            lds2d(xv[4], xv[5],  xa + 32); lds2d(xv[6], xv[7],  xa + 48);
            lds2d(xv[8], xv[9],  xa + 64); lds2d(xv[10], xv[11], xa + 80);
            lds2d(wv[0], wv[1],  wa);      lds2d(wv[2], wv[3],  wa + 16);
            lds2d(wv[4], wv[5],  wa + 32); lds2d(wv[6], wv[7],  wa + 48);
            lds2d(wv[8], wv[9],  wa + 64); lds2d(wv[10], wv[11], wa + 80);
#pragma unroll
            for (int j = 0; j < 12; ++j) fma2(acc, wv[j], xv[j]);
            const int cell = (p < 20) ? p : (p - 20);
            const int half = (p < 20) ? 0 : 1;
            sts64d(xg_base + s * 384 + cell * 16 + half * 8, acc);
        }
        __syncwarp();

        // ---- 8 steps, fully unrolled (s, buffers, offsets all compile-time) ----
#pragma unroll
        for (int s = 0; s < CHUNK; ++s) {
            const u32 hrd = (s & 1) ? h_rd1 : h_rd0;
            const u32 hwr = (s & 1) ? h_my0 : h_my1;

            u64 a01, a23;
            lds2d(a01, a23, myxg + s * 384);
            u64 hq[H_DIM];
            lds2d(hq[0],  hq[1],  hrd);       lds2d(hq[2],  hq[3],  hrd + 16);
            lds2d(hq[4],  hq[5],  hrd + 32);  lds2d(hq[6],  hq[7],  hrd + 48);
            lds2d(hq[8],  hq[9],  hrd + 64);  lds2d(hq[10], hq[11], hrd + 80);
            lds2d(hq[12], hq[13], hrd + 96);  lds2d(hq[14], hq[15], hrd + 112);
            lds2d(hq[16], hq[17], hrd + 128); lds2d(hq[18], hq[19], hrd + 144);
#pragma unroll
            for (int j = 0; j < H_DIM; ++j) {
                fma2(a01, wh01[j], hq[j]);
                fma2(a23, wh23[j], hq[j]);
            }
            float p0, p1, p2, p3;
            unpack2(p0, p1, a01);
            unpack2(p2, p3, a23);
            // computed by all lanes; garbage on lanes >= 20 (never stored)
            const float iv = sig_a(p0), fv = sig_a(p1);
            const float gv = tanh_a(p2), ov = sig_a(p3);
            c = fmaf(fv, c, iv * gv);
            const float h = ov * tanh_a(c);
            if (hLane) sts64d(hwr, pack2(h, h));
            if (oLane && (s > 0 || ch > 0)) *outp = p0;   // out[t-1]
            outp += OS;
            __syncwarp();
        }
    }

    // ---- final out[T-1]: h_511 is in buf 0 ----
    {
        u64 a01, a23d;
        lds2d(a01, a23d, myxg);           // out lanes: (bout[m], 0)
        u64 hq[H_DIM];
        lds2d(hq[0],  hq[1],  h_rd0);       lds2d(hq[2],  hq[3],  h_rd0 + 16);
        lds2d(hq[4],  hq[5],  h_rd0 + 32);  lds2d(hq[6],  hq[7],  h_rd0 + 48);
        lds2d(hq[8],  hq[9],  h_rd0 + 64);  lds2d(hq[10], hq[11], h_rd0 + 80);
        lds2d(hq[12], hq[13], h_rd0 + 96);  lds2d(hq[14], hq[15], h_rd0 + 112);
        lds2d(hq[16], hq[17], h_rd0 + 128); lds2d(hq[18], hq[19], h_rd0 + 144);
#pragma unroll
        for (int j = 0; j < H_DIM; ++j) fma2(a01, wh01[j], hq[j]);
        if (oLane) {
            float v, d; unpack2(v, d, a01);
            *outp = v;                    // outp == out + (T-1)*OS + grow*3 + m
        }
    }
}

extern "C" void kernel_launch(void* const* d_in, const int* in_sizes, int n_in,
                              void* d_out, int out_size) {
    const float* X    = (const float*)d_in[0];
    const float* Wemb = (const float*)d_in[1];
    const float* bemb = (const float*)d_in[2];
    const float* Wih  = (const float*)d_in[3];
    const float* bih  = (const float*)d_in[4];
    const float* Whh  = (const float*)d_in[5];
    const float* bhh  = (const float*)d_in[6];
    const float* Wout = (const float*)d_in[7];
    const float* bout = (const float*)d_in[8];
    float* out = (float*)d_out;

    lstm_tracker_kernel<<<BATCH / 2, 64>>>(X, Wemb, bemb, Wih, bih,
                                           Whh, bhh, Wout, bout, out);
}

// round 10
// speedup vs baseline: 1.3400x; 1.0253x over previous
#include <cuda_runtime.h>
#include <cstdint>

#define T_STEPS 512
#define BATCH   2048
#define IN_DIM  12
#define E_DIM   15
#define H_DIM   20
#define CHUNK   8
#define NCHUNK  (T_STEPS / CHUNK)
#define XS      (BATCH * IN_DIM)
#define OS      (BATCH * 3)

typedef unsigned long long u64;
typedef uint32_t u32;

__device__ __forceinline__ u64 pack2(float x, float y) {
    u64 u; asm("mov.b64 %0, {%1, %2};" : "=l"(u) : "f"(x), "f"(y)); return u;
}
__device__ __forceinline__ void unpack2(float& x, float& y, u64 u) {
    asm("mov.b64 {%0, %1}, %2;" : "=f"(x), "=f"(y) : "l"(u));
}
__device__ __forceinline__ void fma2(u64& d, u64 a, u64 b) {
    asm("fma.rn.f32x2 %0, %1, %2, %0;" : "+l"(d) : "l"(a), "l"(b));
}
__device__ __forceinline__ float tanh_a(float x) {
    float y; asm("tanh.approx.f32 %0, %1;" : "=f"(y) : "f"(x)); return y;
}
__device__ __forceinline__ float sig_a(float x) {
    return fmaf(0.5f, tanh_a(0.5f * x), 0.5f);
}
__device__ __forceinline__ u32 saddr(const void* p) {
    return (u32)__cvta_generic_to_shared(p);
}
__device__ __forceinline__ void lds2d(u64& a, u64& b, u32 addr) {
    asm volatile("ld.shared.v2.b64 {%0, %1}, [%2];" : "=l"(a), "=l"(b) : "r"(addr));
}
__device__ __forceinline__ void sts64d(u32 addr, u64 v) {
    asm volatile("st.shared.b64 [%0], %1;" :: "r"(addr), "l"(v));
}

__global__ void __launch_bounds__(32, 14)
lstm_tracker_kernel(const float* __restrict__ X,
                    const float* __restrict__ Wemb, const float* __restrict__ bemb,
                    const float* __restrict__ Wih,  const float* __restrict__ bih,
                    const float* __restrict__ Whh,  const float* __restrict__ bhh,
                    const float* __restrict__ Wout, const float* __restrict__ bout,
                    float* __restrict__ out)
{
    // one warp per block == one batch row; all smem loads are warp-broadcast
    __shared__ __align__(16) u64 hdup[2][H_DIM];        // (h,h) pairs, ping-pong
    __shared__ __align__(16) u64 xdup[CHUNK][IN_DIM];   // (x,x) pairs, one chunk

    const int lane = threadIdx.x;
    const int grow = blockIdx.x;
    const bool hL = lane < H_DIM;
    const bool oL = (lane >= H_DIM) && (lane < H_DIM + 3);

    // ---- per-lane register weights: 32 operand-pairs x 2 accumulators ----
    // operand vector = [hdup(20 pairs) | xdup(12 pairs)]
    // lane k<20:  w01[j]=(Whh_i[k][j],Whh_f[k][j]), x-part = fused (Wc_i,Wc_f)
    //             w23 similarly for (g,o).  acc a01=(pre_i,pre_f), a23=(pre_g,pre_o)
    // lane 20..22 (m=lane-20): w01[j]=(Wout[m][j],0) -> a01.x = out value. w23=0.
    u64 w01[32], w23[32];
    u64 b01 = 0ull, b23 = 0ull;

    if (hL) {
#pragma unroll
        for (int j = 0; j < H_DIM; ++j) {
            w01[j] = pack2(Whh[lane * H_DIM + j],
                           Whh[(H_DIM + lane) * H_DIM + j]);
            w23[j] = pack2(Whh[(2 * H_DIM + lane) * H_DIM + j],
                           Whh[(3 * H_DIM + lane) * H_DIM + j]);
        }
        float bb[4];
#pragma unroll
        for (int g = 0; g < 4; ++g) {
            const int r = g * H_DIM + lane;
            float b = bih[r] + bhh[r];
#pragma unroll
            for (int e = 0; e < E_DIM; ++e) b += Wih[r * E_DIM + e] * bemb[e];
            bb[g] = b;
        }
        b01 = pack2(bb[0], bb[1]);
        b23 = pack2(bb[2], bb[3]);
#pragma unroll
        for (int j = 0; j < IN_DIM; ++j) {
            float cg[4];
#pragma unroll
            for (int g = 0; g < 4; ++g) {
                float s = 0.f;
#pragma unroll
                for (int e = 0; e < E_DIM; ++e)
                    s += Wih[(g * H_DIM + lane) * E_DIM + e] * Wemb[e * IN_DIM + j];
                cg[g] = s;
            }
            w01[H_DIM + j] = pack2(cg[0], cg[1]);
            w23[H_DIM + j] = pack2(cg[2], cg[3]);
        }
    } else {
#pragma unroll
        for (int j = 0; j < 32; ++j) { w01[j] = 0ull; w23[j] = 0ull; }
        if (oL) {
            const int m = lane - H_DIM;
#pragma unroll
            for (int j = 0; j < H_DIM; ++j)
                w01[j] = pack2(Wout[m * H_DIM + j], 0.f);
            b01 = pack2(bout[m], 0.f);
        }
    }
    if (hL) hdup[0][lane] = 0ull;

    // ---- stage x chunk 0 into smem; prefetch chunk 1 into regs ----
    float xr[3];
#pragma unroll
    for (int m = 0; m < 3; ++m) {
        const int i = lane + 32 * m;
        const int s = i / IN_DIM, j = i - s * IN_DIM;
        const float v = X[(long long)s * XS + (long long)grow * IN_DIM + j];
        xdup[s][j] = pack2(v, v);
    }
#pragma unroll
    for (int m = 0; m < 3; ++m) {
        const int i = lane + 32 * m;
        const int s = i / IN_DIM, j = i - s * IN_DIM;
        xr[m] = X[(long long)(CHUNK + s) * XS + (long long)grow * IN_DIM + j];
    }
    __syncwarp();

    const u32 h0a = saddr(&hdup[0][0]);
    const u32 h1a = saddr(&hdup[1][0]);
    const u32 xa  = saddr(&xdup[0][0]);
    const u32 hw0 = h0a + lane * 8;
    const u32 hw1 = h1a + lane * 8;

    float c = 0.f;
    float* outp = out + (long long)grow * 3 + (lane - H_DIM) - OS;

    for (int ch = 0; ch < NCHUNK; ++ch) {
        // ---- chunk boundary: stage x from regs, prefetch next chunk ----
        if (ch > 0) {
#pragma unroll
            for (int m = 0; m < 3; ++m) {
                const int i = lane + 32 * m;
                const int s = i / IN_DIM, j = i - s * IN_DIM;
                xdup[s][j] = pack2(xr[m], xr[m]);
            }
            if (ch + 1 < NCHUNK) {
                const long long tb = (long long)(ch + 1) * CHUNK;
#pragma unroll
                for (int m = 0; m < 3; ++m) {
                    const int i = lane + 32 * m;
                    const int s = i / IN_DIM, j = i - s * IN_DIM;
                    xr[m] = X[(tb + s) * XS + (long long)grow * IN_DIM + j];
                }
            }
            __syncwarp();
        }

        // ---- 8 fully-unrolled steps; all LDS are warp-broadcast ----
#pragma unroll
        for (int s = 0; s < CHUNK; ++s) {
            const u32 hrd = (s & 1) ? h1a : h0a;
            const u32 hwr = (s & 1) ? hw0 : hw1;

            u64 a01 = b01, a23 = b23;
#pragma unroll
            for (int q = 0; q < 5; ++q) {           // h part: 20 pairs
                u64 e0, e1, e2, e3;
                lds2d(e0, e1, hrd + q * 32);
                lds2d(e2, e3, hrd + q * 32 + 16);
                fma2(a01, w01[4 * q],     e0); fma2(a23, w23[4 * q],     e0);
                fma2(a01, w01[4 * q + 1], e1); fma2(a23, w23[4 * q + 1], e1);
                fma2(a01, w01[4 * q + 2], e2); fma2(a23, w23[4 * q + 2], e2);
                fma2(a01, w01[4 * q + 3], e3); fma2(a23, w23[4 * q + 3], e3);
            }
#pragma unroll
            for (int q = 0; q < 3; ++q) {           // x part: 12 pairs
                u64 e0, e1, e2, e3;
                lds2d(e0, e1, xa + s * 96 + q * 32);
                lds2d(e2, e3, xa + s * 96 + q * 32 + 16);
                fma2(a01, w01[20 + 4 * q],     e0); fma2(a23, w23[20 + 4 * q],     e0);
                fma2(a01, w01[20 + 4 * q + 1], e1); fma2(a23, w23[20 + 4 * q + 1], e1);
                fma2(a01, w01[20 + 4 * q + 2], e2); fma2(a23, w23[20 + 4 * q + 2], e2);
                fma2(a01, w01[20 + 4 * q + 3], e3); fma2(a23, w23[20 + 4 * q + 3], e3);
            }

            float p0, p1, p2, p3;
            unpack2(p0, p1, a01);
            unpack2(p2, p3, a23);
            const float iv = sig_a(p0), fv = sig_a(p1);
            const float gv = tanh_a(p2), ov = sig_a(p3);
            c = fmaf(fv, c, iv * gv);
            const float h = ov * tanh_a(c);
            if (hL) sts64d(hwr, pack2(h, h));
            if (oL && (s > 0 || ch > 0)) *outp = p0;   // out[t-1] = raw a01.x
            outp += OS;
            __syncwarp();
        }
    }

    // ---- final out[T-1]: h_511 lives in hdup[0] ----
    {
        u64 a01 = b01;
#pragma unroll
        for (int q = 0; q < 5; ++q) {
            u64 e0, e1, e2, e3;
            lds2d(e0, e1, h0a + q * 32);
            lds2d(e2, e3, h0a + q * 32 + 16);
            fma2(a01, w01[4 * q],     e0); fma2(a01, w01[4 * q + 1], e1);
            fma2(a01, w01[4 * q + 2], e2); fma2(a01, w01[4 * q + 3], e3);
        }
        if (oL) {
            float v, d; unpack2(v, d, a01);
            *outp = v;
        }
    }
}

extern "C" void kernel_launch(void* const* d_in, const int* in_sizes, int n_in,
                              void* d_out, int out_size) {
    const float* X    = (const float*)d_in[0];
    const float* Wemb = (const float*)d_in[1];
    const float* bemb = (const float*)d_in[2];
    const float* Wih  = (const float*)d_in[3];
    const float* bih  = (const float*)d_in[4];
    const float* Whh  = (const float*)d_in[5];
    const float* bhh  = (const float*)d_in[6];
    const float* Wout = (const float*)d_in[7];
    const float* bout = (const float*)d_in[8];
    float* out = (float*)d_out;

    lstm_tracker_kernel<<<BATCH, 32>>>(X, Wemb, bemb, Wih, bih,
                                       Whh, bhh, Wout, bout, out);
}

// round 11
// speedup vs baseline: 1.4309x; 1.0678x over previous
#include <cuda_runtime.h>
#include <cstdint>

#define T_STEPS 512
#define BATCH   2048
#define IN_DIM  12
#define E_DIM   15
#define H_DIM   20
#define XS      (BATCH * IN_DIM)
#define OS      (BATCH * 3)
#define TCHUNKS 8
#define TPERC   (T_STEPS / TCHUNKS)   // 64

typedef unsigned long long u64;
typedef uint32_t u32;

// Scratch: x-gate pre-activations, float4 (i,f,g,o) per (t, b, cell).
// Padded by 4 timesteps so kernel2's prefetch never needs a bounds check.
__device__ __align__(16) float4 g_xg[(T_STEPS + 4) * BATCH * H_DIM];

__device__ __forceinline__ u64 pack2(float x, float y) {
    u64 u; asm("mov.b64 %0, {%1, %2};" : "=l"(u) : "f"(x), "f"(y)); return u;
}
__device__ __forceinline__ void unpack2(float& x, float& y, u64 u) {
    asm("mov.b64 {%0, %1}, %2;" : "=f"(x), "=f"(y) : "l"(u));
}
__device__ __forceinline__ void fma2(u64& d, u64 a, u64 b) {
    asm("fma.rn.f32x2 %0, %1, %2, %0;" : "+l"(d) : "l"(a), "l"(b));
}
__device__ __forceinline__ float hsum2(u64 u) {
    float x, y; unpack2(x, y, u); return x + y;
}
__device__ __forceinline__ float tanh_a(float x) {
    float y; asm("tanh.approx.f32 %0, %1;" : "=f"(y) : "f"(x)); return y;
}
__device__ __forceinline__ float sig_a(float x) {
    return fmaf(0.5f, tanh_a(0.5f * x), 0.5f);
}
__device__ __forceinline__ u32 saddr(const void* p) {
    return (u32)__cvta_generic_to_shared(p);
}
__device__ __forceinline__ void lds2d(u64& a, u64& b, u32 addr) {
    asm volatile("ld.shared.v2.b64 {%0, %1}, [%2];" : "=l"(a), "=l"(b) : "r"(addr));
}
__device__ __forceinline__ void sts64d(u32 addr, u64 v) {
    asm volatile("st.shared.b64 [%0], %1;" :: "r"(addr), "l"(v));
}
__device__ __forceinline__ void ldg2(u64& a, u64& b, const void* p) {
    asm volatile("ld.global.v2.b64 {%0, %1}, [%2];" : "=l"(a), "=l"(b) : "l"(p));
}

// ===================== Kernel 1: x-gate precompute =====================
// warp = (batch row b, 64-step t-chunk). Lane k<20 owns cell k (4 gates).
__global__ void __launch_bounds__(32, 16)
xgate_kernel(const float* __restrict__ X,
             const float* __restrict__ Wemb, const float* __restrict__ bemb,
             const float* __restrict__ Wih,  const float* __restrict__ bih,
             const float* __restrict__ bhh)
{
    const int lane = threadIdx.x;
    const int b    = blockIdx.x;
    const int tc   = blockIdx.y;
    const int k    = (lane < H_DIM) ? lane : 0;

    // fused weights Wc = Wih@Wemb (pairs over x), fused bias
    u64 wg[4][6]; float bc[4];
#pragma unroll
    for (int g = 0; g < 4; ++g) {
        const int r = g * H_DIM + k;
        float bb = bih[r] + bhh[r];
#pragma unroll
        for (int e = 0; e < E_DIM; ++e) bb += Wih[r * E_DIM + e] * bemb[e];
        bc[g] = bb;
#pragma unroll
        for (int jj = 0; jj < 6; ++jj) {
            float c0 = 0.f, c1 = 0.f;
#pragma unroll
            for (int e = 0; e < E_DIM; ++e) {
                const float wie = Wih[r * E_DIM + e];
                c0 += wie * Wemb[e * IN_DIM + 2 * jj];
                c1 += wie * Wemb[e * IN_DIM + 2 * jj + 1];
            }
            wg[g][jj] = pack2(c0, c1);
        }
    }

    const float* xp = X + (long long)(tc * TPERC) * XS + (long long)b * IN_DIM;
    float4* op = g_xg + ((long long)(tc * TPERC) * BATCH + b) * H_DIM + k;

    // 2-deep x pipeline (A/B register sets), 2-step unroll
    u64 xa0, xa1, xa2, xa3, xa4, xa5;
    ldg2(xa0, xa1, xp); ldg2(xa2, xa3, xp + 4); ldg2(xa4, xa5, xp + 8);
    xp += XS;

#pragma unroll 1
    for (int it = 0; it < TPERC; it += 2) {
        u64 xb0, xb1, xb2, xb3, xb4, xb5;
        ldg2(xb0, xb1, xp); ldg2(xb2, xb3, xp + 4); ldg2(xb4, xb5, xp + 8);
        xp += XS;
        {
            u64 a0 = pack2(bc[0], 0.f), a1 = pack2(bc[1], 0.f);
            u64 a2 = pack2(bc[2], 0.f), a3 = pack2(bc[3], 0.f);
            fma2(a0, wg[0][0], xa0); fma2(a1, wg[1][0], xa0); fma2(a2, wg[2][0], xa0); fma2(a3, wg[3][0], xa0);
            fma2(a0, wg[0][1], xa1); fma2(a1, wg[1][1], xa1); fma2(a2, wg[2][1], xa1); fma2(a3, wg[3][1], xa1);
            fma2(a0, wg[0][2], xa2); fma2(a1, wg[1][2], xa2); fma2(a2, wg[2][2], xa2); fma2(a3, wg[3][2], xa2);
            fma2(a0, wg[0][3], xa3); fma2(a1, wg[1][3], xa3); fma2(a2, wg[2][3], xa3); fma2(a3, wg[3][3], xa3);
            fma2(a0, wg[0][4], xa4); fma2(a1, wg[1][4], xa4); fma2(a2, wg[2][4], xa4); fma2(a3, wg[3][4], xa4);
            fma2(a0, wg[0][5], xa5); fma2(a1, wg[1][5], xa5); fma2(a2, wg[2][5], xa5); fma2(a3, wg[3][5], xa5);
            float4 r; r.x = hsum2(a0); r.y = hsum2(a1); r.z = hsum2(a2); r.w = hsum2(a3);
            if (lane < H_DIM) *op = r;
            op += BATCH * H_DIM;
        }
        ldg2(xa0, xa1, xp); ldg2(xa2, xa3, xp + 4); ldg2(xa4, xa5, xp + 8);
        xp += XS;
        {
            u64 a0 = pack2(bc[0], 0.f), a1 = pack2(bc[1], 0.f);
            u64 a2 = pack2(bc[2], 0.f), a3 = pack2(bc[3], 0.f);
            fma2(a0, wg[0][0], xb0); fma2(a1, wg[1][0], xb0); fma2(a2, wg[2][0], xb0); fma2(a3, wg[3][0], xb0);
            fma2(a0, wg[0][1], xb1); fma2(a1, wg[1][1], xb1); fma2(a2, wg[2][1], xb1); fma2(a3, wg[3][1], xb1);
            fma2(a0, wg[0][2], xb2); fma2(a1, wg[1][2], xb2); fma2(a2, wg[2][2], xb2); fma2(a3, wg[3][2], xb2);
            fma2(a0, wg[0][3], xb3); fma2(a1, wg[1][3], xb3); fma2(a2, wg[2][3], xb3); fma2(a3, wg[3][3], xb3);
            fma2(a0, wg[0][4], xb4); fma2(a1, wg[1][4], xb4); fma2(a2, wg[2][4], xb4); fma2(a3, wg[3][4], xb4);
            fma2(a0, wg[0][5], xb5); fma2(a1, wg[1][5], xb5); fma2(a2, wg[2][5], xb5); fma2(a3, wg[3][5], xb5);
            float4 r; r.x = hsum2(a0); r.y = hsum2(a1); r.z = hsum2(a2); r.w = hsum2(a3);
            if (lane < H_DIM) *op = r;
            op += BATCH * H_DIM;
        }
    }
}

// ===================== Kernel 2: recurrence =====================
// warp = batch row. Lane k<20: cell k (all 4 gates via 2 pair-accumulators).
// Lanes 20-22: output projection overlay (runs the same instruction stream).
__global__ void __launch_bounds__(32, 14)
lstm_kernel(const float* __restrict__ Whh,
            const float* __restrict__ Wout, const float* __restrict__ bout,
            float* __restrict__ out)
{
    __shared__ __align__(16) u64 hdup[2][H_DIM];   // (h,h) pairs, ping-pong

    const int lane = threadIdx.x;
    const int grow = blockIdx.x;
    const bool hL = lane < H_DIM;
    const bool oL = (lane >= H_DIM) && (lane < H_DIM + 3);
    const int k   = hL ? lane : 0;

    u64 w01[H_DIM], w23[H_DIM];
    u64 bO = 0ull;
    if (hL) {
#pragma unroll
        for (int j = 0; j < H_DIM; ++j) {
            w01[j] = pack2(Whh[lane * H_DIM + j],            Whh[(H_DIM + lane) * H_DIM + j]);
            w23[j] = pack2(Whh[(2 * H_DIM + lane) * H_DIM + j], Whh[(3 * H_DIM + lane) * H_DIM + j]);
        }
    } else {
#pragma unroll
        for (int j = 0; j < H_DIM; ++j) { w01[j] = 0ull; w23[j] = 0ull; }
        if (oL) {
            const int m = lane - H_DIM;
#pragma unroll
            for (int j = 0; j < H_DIM; ++j) w01[j] = pack2(Wout[m * H_DIM + j], 0.f);
            bO = pack2(bout[m], 0.f);
        }
    }
    if (hL) hdup[0][lane] = 0ull;
    __syncwarp();

    const u32 h0a = saddr(&hdup[0][0]);
    const u32 h1a = saddr(&hdup[1][0]);
    const u32 hw0 = h0a + lane * 8;
    const u32 hw1 = h1a + lane * 8;

    const long long gstride = (long long)BATCH * H_DIM;     // float4s per t
    const float4* gp = g_xg + (long long)grow * H_DIM + k;

    // prefetch xg for t = 0..3
    u64 pa0, pa1, pb0, pb1, pc0, pc1, pd0, pd1;
    ldg2(pa0, pa1, gp);
    ldg2(pb0, pb1, gp + gstride);
    ldg2(pc0, pc1, gp + 2 * gstride);
    ldg2(pd0, pd1, gp + 3 * gstride);
    gp += 4 * gstride;

    float c = 0.f;
    float* outp = out + (long long)grow * 3 + (lane - H_DIM) - OS;

#define STEP(PX0, PX1, HRD, HWR, DOOUT)                                        \
    do {                                                                       \
        u64 a01 = hL ? (PX0) : bO;                                             \
        u64 a23 = (PX1);                                                       \
        u64 e0, e1, e2, e3;                                                    \
        lds2d(e0, e1, (HRD));        lds2d(e2, e3, (HRD) + 16);                \
        fma2(a01, w01[0], e0); fma2(a23, w23[0], e0);                          \
        fma2(a01, w01[1], e1); fma2(a23, w23[1], e1);                          \
        fma2(a01, w01[2], e2); fma2(a23, w23[2], e2);                          \
        fma2(a01, w01[3], e3); fma2(a23, w23[3], e3);                          \
        lds2d(e0, e1, (HRD) + 32);   lds2d(e2, e3, (HRD) + 48);                \
        fma2(a01, w01[4], e0); fma2(a23, w23[4], e0);                          \
        fma2(a01, w01[5], e1); fma2(a23, w23[5], e1);                          \
        fma2(a01, w01[6], e2); fma2(a23, w23[6], e2);                          \
        fma2(a01, w01[7], e3); fma2(a23, w23[7], e3);                          \
        lds2d(e0, e1, (HRD) + 64);   lds2d(e2, e3, (HRD) + 80);                \
        fma2(a01, w01[8],  e0); fma2(a23, w23[8],  e0);                        \
        fma2(a01, w01[9],  e1); fma2(a23, w23[9],  e1);                        \
        fma2(a01, w01[10], e2); fma2(a23, w23[10], e2);                        \
        fma2(a01, w01[11], e3); fma2(a23, w23[11], e3);                        \
        lds2d(e0, e1, (HRD) + 96);   lds2d(e2, e3, (HRD) + 112);               \
        fma2(a01, w01[12], e0); fma2(a23, w23[12], e0);                        \
        fma2(a01, w01[13], e1); fma2(a23, w23[13], e1);                        \
        fma2(a01, w01[14], e2); fma2(a23, w23[14], e2);                        \
        fma2(a01, w01[15], e3); fma2(a23, w23[15], e3);                        \
        lds2d(e0, e1, (HRD) + 128);  lds2d(e2, e3, (HRD) + 144);               \
        fma2(a01, w01[16], e0); fma2(a23, w23[16], e0);                        \
        fma2(a01, w01[17], e1); fma2(a23, w23[17], e1);                        \
        fma2(a01, w01[18], e2); fma2(a23, w23[18], e2);                        \
        fma2(a01, w01[19], e3); fma2(a23, w23[19], e3);                        \
        float p0, p1, p2, p3;                                                  \
        unpack2(p0, p1, a01); unpack2(p2, p3, a23);                            \
        const float iv = sig_a(p0), fv = sig_a(p1);                            \
        const float gv = tanh_a(p2), ov = sig_a(p3);                           \
        c = fmaf(fv, c, iv * gv);                                              \
        const float h = ov * tanh_a(c);                                        \
        if (hL) sts64d((HWR), pack2(h, h));                                    \
        if (oL && (DOOUT)) *outp = p0;                                         \
        outp += OS;                                                            \
        ldg2((PX0), (PX1), gp); gp += gstride;                                 \
        __syncwarp();                                                          \
    } while (0)

    // first quad: suppress out-store at t=0 (h_{-1} has no output)
    STEP(pa0, pa1, h0a, hw1, false);
    STEP(pb0, pb1, h1a, hw0, true);
    STEP(pc0, pc1, h0a, hw1, true);
    STEP(pd0, pd1, h1a, hw0, true);
#pragma unroll 1
    for (int t4 = 4; t4 < T_STEPS; t4 += 4) {
        STEP(pa0, pa1, h0a, hw1, true);
        STEP(pb0, pb1, h1a, hw0, true);
        STEP(pc0, pc1, h0a, hw1, true);
        STEP(pd0, pd1, h1a, hw0, true);
    }
#undef STEP

    // final out[T-1] from h_511 (written to buf 0 at t=511)
    {
        u64 a01 = bO;
        u64 e0, e1, e2, e3;
#pragma unroll
        for (int q = 0; q < 5; ++q) {
            lds2d(e0, e1, h0a + q * 32);
            lds2d(e2, e3, h0a + q * 32 + 16);
            fma2(a01, w01[4 * q],     e0); fma2(a01, w01[4 * q + 1], e1);
            fma2(a01, w01[4 * q + 2], e2); fma2(a01, w01[4 * q + 3], e3);
        }
        if (oL) {
            float v, d; unpack2(v, d, a01);
            *outp = v;
        }
    }
}

extern "C" void kernel_launch(void* const* d_in, const int* in_sizes, int n_in,
                              void* d_out, int out_size) {
    const float* X    = (const float*)d_in[0];
    const float* Wemb = (const float*)d_in[1];
    const float* bemb = (const float*)d_in[2];
    const float* Wih  = (const float*)d_in[3];
    const float* bih  = (const float*)d_in[4];
    const float* Whh  = (const float*)d_in[5];
    const float* bhh  = (const float*)d_in[6];
    const float* Wout = (const float*)d_in[7];
    const float* bout = (const float*)d_in[8];
    float* out = (float*)d_out;

    dim3 g1(BATCH, TCHUNKS);
    xgate_kernel<<<g1, 32>>>(X, Wemb, bemb, Wih, bih, bhh);
    lstm_kernel<<<BATCH, 32>>>(Whh, Wout, bout, out);
}

// round 12
// speedup vs baseline: 1.7110x; 1.1958x over previous
#include <cuda_runtime.h>
#include <cuda_fp16.h>
#include <cstdint>

#define T_STEPS 512
#define BATCH   2048
#define IN_DIM  12
#define E_DIM   15
#define H_DIM   20
#define XS      (BATCH * IN_DIM)
#define OS      (BATCH * 3)
#define TCHUNKS 8
#define TPERC   (T_STEPS / TCHUNKS)   // 64
#define TPAD    (T_STEPS + 4)         // prefetch pad

typedef unsigned long long u64;
typedef uint32_t u32;

// Scratch: x-gate pre-activations as half4 (i,f,g,o) = one u64 per (b,t,cell).
// Layout [b][t][cell] so each recurrence warp streams contiguously.
__device__ __align__(16) u64   g_xg[(size_t)BATCH * TPAD * H_DIM];
// Fused x->gate weights (Wih@Wemb) in j-pair form, and fused biases.
__device__ __align__(16) u64   g_wcx[4][H_DIM][6];
__device__ __align__(16) float4 g_bc4[H_DIM];

__device__ __forceinline__ u64 pack2(float x, float y) {
    u64 u; asm("mov.b64 %0, {%1, %2};" : "=l"(u) : "f"(x), "f"(y)); return u;
}
__device__ __forceinline__ void unpack2(float& x, float& y, u64 u) {
    asm("mov.b64 {%0, %1}, %2;" : "=f"(x), "=f"(y) : "l"(u));
}
__device__ __forceinline__ u64 pack2u(u32 lo, u32 hi) {
    u64 u; asm("mov.b64 %0, {%1, %2};" : "=l"(u) : "r"(lo), "r"(hi)); return u;
}
__device__ __forceinline__ void unpack2u(u32& lo, u32& hi, u64 u) {
    asm("mov.b64 {%0, %1}, %2;" : "=r"(lo), "=r"(hi) : "l"(u));
}
__device__ __forceinline__ void fma2(u64& d, u64 a, u64 b) {
    asm("fma.rn.f32x2 %0, %1, %2, %0;" : "+l"(d) : "l"(a), "l"(b));
}
__device__ __forceinline__ void add2(u64& d, u64 a) {
    asm("add.rn.f32x2 %0, %0, %1;" : "+l"(d) : "l"(a));
}
__device__ __forceinline__ float hsum2(u64 u) {
    float x, y; unpack2(x, y, u); return x + y;
}
__device__ __forceinline__ float tanh_a(float x) {
    float y; asm("tanh.approx.f32 %0, %1;" : "=f"(y) : "f"(x)); return y;
}
__device__ __forceinline__ float sig_a(float x) {
    return fmaf(0.5f, tanh_a(0.5f * x), 0.5f);
}
__device__ __forceinline__ u32 saddr(const void* p) {
    return (u32)__cvta_generic_to_shared(p);
}
__device__ __forceinline__ void lds2d(u64& a, u64& b, u32 addr) {
    asm volatile("ld.shared.v2.b64 {%0, %1}, [%2];" : "=l"(a), "=l"(b) : "r"(addr));
}
__device__ __forceinline__ void sts64d(u32 addr, u64 v) {
    asm volatile("st.shared.b64 [%0], %1;" :: "r"(addr), "l"(v));
}
__device__ __forceinline__ void ldg2(u64& a, u64& b, const void* p) {
    asm volatile("ld.global.v2.b64 {%0, %1}, [%2];" : "=l"(a), "=l"(b) : "l"(p));
}
__device__ __forceinline__ void ldg1(u64& a, const void* p) {
    asm volatile("ld.global.b64 %0, [%1];" : "=l"(a) : "l"(p));
}
__device__ __forceinline__ float2 h2f(u32 v) {
    __half2 h = *reinterpret_cast<__half2*>(&v);
    return __half22float2(h);
}

// ============ Kernel 0: fuse Wc = Wih@Wemb, bc once ============
__global__ void prep_kernel(const float* __restrict__ Wemb, const float* __restrict__ bemb,
                            const float* __restrict__ Wih,  const float* __restrict__ bih,
                            const float* __restrict__ bhh)
{
    const int tid = threadIdx.x;
    for (int i = tid; i < 480; i += blockDim.x) {
        const int g = i / 120, rem = i - g * 120;
        const int k = rem / 6, jj = rem - k * 6;
        const int r = g * H_DIM + k;
        float c0 = 0.f, c1 = 0.f;
#pragma unroll
        for (int e = 0; e < E_DIM; ++e) {
            const float wie = Wih[r * E_DIM + e];
            c0 += wie * Wemb[e * IN_DIM + 2 * jj];
            c1 += wie * Wemb[e * IN_DIM + 2 * jj + 1];
        }
        g_wcx[g][k][jj] = pack2(c0, c1);
    }
    if (tid < H_DIM) {
        float4 b4;
        float* bp = &b4.x;
#pragma unroll
        for (int g = 0; g < 4; ++g) {
            const int r = g * H_DIM + tid;
            float b = bih[r] + bhh[r];
#pragma unroll
            for (int e = 0; e < E_DIM; ++e) b += Wih[r * E_DIM + e] * bemb[e];
            bp[g] = b;
        }
        g_bc4[tid] = b4;
    }
}

// ============ Kernel 1: x-gate precompute -> half4 scratch ============
__global__ void __launch_bounds__(32, 16)
xgate_kernel(const float* __restrict__ X)
{
    const int lane = threadIdx.x;
    const int b    = blockIdx.x;
    const int tc   = blockIdx.y;
    const int k    = (lane < H_DIM) ? lane : 0;

    u64 wg[4][6];
#pragma unroll
    for (int g = 0; g < 4; ++g)
#pragma unroll
        for (int jj = 0; jj < 6; ++jj) wg[g][jj] = g_wcx[g][k][jj];
    const float4 b4 = g_bc4[k];

    const float* xp = X + (long long)(tc * TPERC) * XS + (long long)b * IN_DIM;
    u64* op = g_xg + ((size_t)b * TPAD + tc * TPERC) * H_DIM + k;

    u64 xa0, xa1, xa2, xa3, xa4, xa5;
    ldg2(xa0, xa1, xp); ldg2(xa2, xa3, xp + 4); ldg2(xa4, xa5, xp + 8);
    xp += XS;

#define XGBODY(X0, X1, X2, X3, X4, X5)                                          \
    do {                                                                        \
        u64 a0 = pack2(b4.x, 0.f), a1 = pack2(b4.y, 0.f);                       \
        u64 a2 = pack2(b4.z, 0.f), a3 = pack2(b4.w, 0.f);                       \
        fma2(a0, wg[0][0], X0); fma2(a1, wg[1][0], X0); fma2(a2, wg[2][0], X0); fma2(a3, wg[3][0], X0); \
        fma2(a0, wg[0][1], X1); fma2(a1, wg[1][1], X1); fma2(a2, wg[2][1], X1); fma2(a3, wg[3][1], X1); \
        fma2(a0, wg[0][2], X2); fma2(a1, wg[1][2], X2); fma2(a2, wg[2][2], X2); fma2(a3, wg[3][2], X2); \
        fma2(a0, wg[0][3], X3); fma2(a1, wg[1][3], X3); fma2(a2, wg[2][3], X3); fma2(a3, wg[3][3], X3); \
        fma2(a0, wg[0][4], X4); fma2(a1, wg[1][4], X4); fma2(a2, wg[2][4], X4); fma2(a3, wg[3][4], X4); \
        fma2(a0, wg[0][5], X5); fma2(a1, wg[1][5], X5); fma2(a2, wg[2][5], X5); fma2(a3, wg[3][5], X5); \
        __half2 hl = __floats2half2_rn(hsum2(a0), hsum2(a1));                   \
        __half2 hh = __floats2half2_rn(hsum2(a2), hsum2(a3));                   \
        const u64 v = pack2u(*reinterpret_cast<u32*>(&hl),                      \
                             *reinterpret_cast<u32*>(&hh));                     \
        if (lane < H_DIM) *op = v;                                              \
        op += H_DIM;                                                            \
    } while (0)

#pragma unroll 1
    for (int it = 0; it < TPERC; it += 2) {
        u64 xb0, xb1, xb2, xb3, xb4, xb5;
        ldg2(xb0, xb1, xp); ldg2(xb2, xb3, xp + 4); ldg2(xb4, xb5, xp + 8);
        xp += XS;
        XGBODY(xa0, xa1, xa2, xa3, xa4, xa5);
        ldg2(xa0, xa1, xp); ldg2(xa2, xa3, xp + 4); ldg2(xa4, xa5, xp + 8);
        xp += XS;
        XGBODY(xb0, xb1, xb2, xb3, xb4, xb5);
    }
#undef XGBODY
}

// ============ Kernel 2: recurrence ============
__global__ void __launch_bounds__(32, 14)
lstm_kernel(const float* __restrict__ Whh,
            const float* __restrict__ Wout, const float* __restrict__ bout,
            float* __restrict__ out)
{
    __shared__ __align__(16) u64 hdup[2][H_DIM];   // (h,h) pairs, ping-pong

    const int lane = threadIdx.x;
    const int grow = blockIdx.x;
    const bool hL = lane < H_DIM;
    const bool oL = (lane >= H_DIM) && (lane < H_DIM + 3);
    const int k   = hL ? lane : 0;

    u64 w01[H_DIM], w23[H_DIM];
    u64 bO = 0ull;
    if (hL) {
#pragma unroll
        for (int j = 0; j < H_DIM; ++j) {
            w01[j] = pack2(Whh[lane * H_DIM + j],               Whh[(H_DIM + lane) * H_DIM + j]);
            w23[j] = pack2(Whh[(2 * H_DIM + lane) * H_DIM + j], Whh[(3 * H_DIM + lane) * H_DIM + j]);
        }
    } else {
#pragma unroll
        for (int j = 0; j < H_DIM; ++j) { w01[j] = 0ull; w23[j] = 0ull; }
        if (oL) {
            const int m = lane - H_DIM;
#pragma unroll
            for (int j = 0; j < H_DIM; ++j) w01[j] = pack2(Wout[m * H_DIM + j], 0.f);
            bO = pack2(bout[m], 0.f);
        }
    }
    if (hL) hdup[0][lane] = 0ull;
    __syncwarp();

    const u32 h0a = saddr(&hdup[0][0]);
    const u32 h1a = saddr(&hdup[1][0]);
    const u32 hw0 = h0a + lane * 8;
    const u32 hw1 = h1a + lane * 8;

    const u64* gp = g_xg + (size_t)grow * TPAD * H_DIM + k;
    u64 pa, pb, pc, pd;
    ldg1(pa, gp);
    ldg1(pb, gp + H_DIM);
    ldg1(pc, gp + 2 * H_DIM);
    ldg1(pd, gp + 3 * H_DIM);
    gp += 4 * H_DIM;

    float c = 0.f;
    float* outp = out + (long long)grow * 3 + (lane - H_DIM) - OS;

#define STEP(PX, HRD, HWR, DOOUT)                                              \
    do {                                                                       \
        u32 xl, xh; unpack2u(xl, xh, (PX));                                    \
        const float2 flo = h2f(xl);                                            \
        const float2 fhi = h2f(xh);                                            \
        u64 a01 = hL ? pack2(flo.x, flo.y) : bO;                               \
        u64 a23 = pack2(fhi.x, fhi.y);                                         \
        u64 a01b = 0ull, a23b = 0ull;                                          \
        u64 e0, e1, e2, e3;                                                    \
        lds2d(e0, e1, (HRD));        lds2d(e2, e3, (HRD) + 16);                \
        fma2(a01, w01[0], e0); fma2(a23, w23[0], e0);                          \
        fma2(a01, w01[1], e1); fma2(a23, w23[1], e1);                          \
        fma2(a01, w01[2], e2); fma2(a23, w23[2], e2);                          \
        fma2(a01, w01[3], e3); fma2(a23, w23[3], e3);                          \
        lds2d(e0, e1, (HRD) + 32);   lds2d(e2, e3, (HRD) + 48);                \
        fma2(a01, w01[4], e0); fma2(a23, w23[4], e0);                          \
        fma2(a01, w01[5], e1); fma2(a23, w23[5], e1);                          \
        fma2(a01, w01[6], e2); fma2(a23, w23[6], e2);                          \
        fma2(a01, w01[7], e3); fma2(a23, w23[7], e3);                          \
        lds2d(e0, e1, (HRD) + 64);   lds2d(e2, e3, (HRD) + 80);                \
        fma2(a01, w01[8],  e0); fma2(a23, w23[8],  e0);                        \
        fma2(a01, w01[9],  e1); fma2(a23, w23[9],  e1);                        \
        fma2(a01b, w01[10], e2); fma2(a23b, w23[10], e2);                      \
        fma2(a01b, w01[11], e3); fma2(a23b, w23[11], e3);                      \
        lds2d(e0, e1, (HRD) + 96);   lds2d(e2, e3, (HRD) + 112);               \
        fma2(a01b, w01[12], e0); fma2(a23b, w23[12], e0);                      \
        fma2(a01b, w01[13], e1); fma2(a23b, w23[13], e1);                      \
        fma2(a01b, w01[14], e2); fma2(a23b, w23[14], e2);                      \
        fma2(a01b, w01[15], e3); fma2(a23b, w23[15], e3);                      \
        lds2d(e0, e1, (HRD) + 128);  lds2d(e2, e3, (HRD) + 144);               \
        fma2(a01b, w01[16], e0); fma2(a23b, w23[16], e0);                      \
        fma2(a01b, w01[17], e1); fma2(a23b, w23[17], e1);                      \
        fma2(a01b, w01[18], e2); fma2(a23b, w23[18], e2);                      \
        fma2(a01b, w01[19], e3); fma2(a23b, w23[19], e3);                      \
        add2(a01, a01b); add2(a23, a23b);                                      \
        float p0, p1, p2, p3;                                                  \
        unpack2(p0, p1, a01); unpack2(p2, p3, a23);                            \
        const float iv = sig_a(p0), fv = sig_a(p1);                            \
        const float gv = tanh_a(p2), ov = sig_a(p3);                           \
        c = fmaf(fv, c, iv * gv);                                              \
        const float h = ov * tanh_a(c);                                        \
        if (hL) sts64d((HWR), pack2(h, h));                                    \
        if (oL && (DOOUT)) *outp = p0;                                         \
        outp += OS;                                                            \
        ldg1((PX), gp); gp += H_DIM;                                           \
        __syncwarp();                                                          \
    } while (0)

    STEP(pa, h0a, hw1, false);
    STEP(pb, h1a, hw0, true);
    STEP(pc, h0a, hw1, true);
    STEP(pd, h1a, hw0, true);
#pragma unroll 1
    for (int t4 = 4; t4 < T_STEPS; t4 += 4) {
        STEP(pa, h0a, hw1, true);
        STEP(pb, h1a, hw0, true);
        STEP(pc, h0a, hw1, true);
        STEP(pd, h1a, hw0, true);
    }
#undef STEP

    // final out[T-1] from h_511 (in buf 0)
    {
        u64 a01 = bO;
        u64 e0, e1, e2, e3;
#pragma unroll
        for (int q = 0; q < 5; ++q) {
            lds2d(e0, e1, h0a + q * 32);
            lds2d(e2, e3, h0a + q * 32 + 16);
            fma2(a01, w01[4 * q],     e0); fma2(a01, w01[4 * q + 1], e1);
            fma2(a01, w01[4 * q + 2], e2); fma2(a01, w01[4 * q + 3], e3);
        }
        if (oL) {
            float v, d; unpack2(v, d, a01);
            *outp = v;
        }
    }
}

extern "C" void kernel_launch(void* const* d_in, const int* in_sizes, int n_in,
                              void* d_out, int out_size) {
    const float* X    = (const float*)d_in[0];
    const float* Wemb = (const float*)d_in[1];
    const float* bemb = (const float*)d_in[2];
    const float* Wih  = (const float*)d_in[3];
    const float* bih  = (const float*)d_in[4];
    const float* Whh  = (const float*)d_in[5];
    const float* bhh  = (const float*)d_in[6];
    const float* Wout = (const float*)d_in[7];
    const float* bout = (const float*)d_in[8];
    float* out = (float*)d_out;

    prep_kernel<<<1, 256>>>(Wemb, bemb, Wih, bih, bhh);
    dim3 g1(BATCH, TCHUNKS);
    xgate_kernel<<<g1, 32>>>(X);
    lstm_kernel<<<BATCH, 32>>>(Whh, Wout, bout, out);
}